// round 1
// baseline (speedup 1.0000x reference)
#include <cuda_runtime.h>
#include <math.h>

#define NB 2
#define NH 8
#define SQ 1024
#define DH 64
#define DM 512
#define NREL 65
#define PCLIP 32

// ---------------- scratch (device globals: no allocation allowed) ----------
__device__ float g_table[NREL * DH];            // sin-cos rel-pos table
__device__ float g_q[NB * NH * SQ * DH];        // [B,H,S,DH]
__device__ float g_k[NB * NH * SQ * DH];
__device__ float g_v[NB * NH * SQ * DH];
__device__ float g_att[NB * SQ * DM];           // attention out, [B,S,DM]
__device__ float g_x[NB * SQ * DM];             // pre-LN activations

// ---------------- sincos table -------------------------------------------
__global__ void table_kernel() {
    int i = blockIdx.x * blockDim.x + threadIdx.x;
    if (i >= NREL * DH) return;
    int pos = i / DH, d = i % DH;
    float freq = expf((float)(d & ~1) * (-logf(10000.0f) / (float)DH));
    float a = (float)pos * freq;
    g_table[i] = (d & 1) ? cosf(a) : sinf(a);
}

// ---------------- GEMM: C = A[M,K] @ W[N,K]^T + bias ----------------------
// MODE 0: scatter to qkv layout [B,H,S,DH] (dst picked by sel)
// MODE 1: A = g_att, dst = g_x, adds residual (query)
template <int MODE>
__global__ void gemm64(const float* __restrict__ A_in,
                       const float* __restrict__ W,
                       const float* __restrict__ bias,
                       const float* __restrict__ resid,
                       int sel, int M, int N, int K) {
    __shared__ __align__(16) float As[16][68];
    __shared__ __align__(16) float Bs[16][68];

    const float* A = (MODE == 0) ? A_in : g_att;
    float* dst;
    if (MODE == 0) dst = (sel == 0) ? g_q : (sel == 1) ? g_k : g_v;
    else           dst = g_x;

    int m0 = blockIdx.y * 64;
    int n0 = blockIdx.x * 64;
    int t  = threadIdx.x;
    int ty = t >> 4, tx = t & 15;

    float acc[4][4];
#pragma unroll
    for (int i = 0; i < 4; i++)
#pragma unroll
        for (int j = 0; j < 4; j++) acc[i][j] = 0.f;

    for (int k0 = 0; k0 < K; k0 += 16) {
#pragma unroll
        for (int p = 0; p < 4; p++) {
            int flat = t + p * 256;
            int kk = flat & 15, mm = flat >> 4;
            As[kk][mm] = A[(m0 + mm) * K + k0 + kk];
            Bs[kk][mm] = W[(n0 + mm) * K + k0 + kk];
        }
        __syncthreads();
#pragma unroll
        for (int kk = 0; kk < 16; kk++) {
            float4 a4 = *(const float4*)&As[kk][ty * 4];
            float4 b4 = *(const float4*)&Bs[kk][tx * 4];
            float av[4] = {a4.x, a4.y, a4.z, a4.w};
            float bv[4] = {b4.x, b4.y, b4.z, b4.w};
#pragma unroll
            for (int i = 0; i < 4; i++)
#pragma unroll
                for (int j = 0; j < 4; j++) acc[i][j] += av[i] * bv[j];
        }
        __syncthreads();
    }

#pragma unroll
    for (int i = 0; i < 4; i++) {
        int m = m0 + ty * 4 + i;
#pragma unroll
        for (int j = 0; j < 4; j++) {
            int n = n0 + tx * 4 + j;
            float v = acc[i][j] + bias[n];
            if (MODE == 0) {
                int b = m >> 10, s = m & (SQ - 1);
                int h = n >> 6,  d = n & 63;
                dst[(((b * NH + h) * SQ) + s) * DH + d] = v;
            } else {
                dst[m * N + n] = v + resid[m * N + n];
            }
        }
    }
}

// ---------------- attention ----------------------------------------------
#define BQ 32
#define KT 128
#define KT_STRIDE 132
#define QS_STRIDE 36
#define RB_STRIDE 34

#define OFF_SC 0
#define OFF_KT (BQ * SQ)                    /* 32768  */
#define OFF_QS (OFF_KT + 64 * KT_STRIDE)    /* +8448  */
#define OFF_RB (OFF_QS + 64 * QS_STRIDE)    /* +2304  */
#define SMEM_FLOATS (OFF_RB + BQ * RB_STRIDE)
#define ATTN_SMEM_BYTES (SMEM_FLOATS * 4)

__global__ void attn_kernel() {
    extern __shared__ __align__(16) float sm[];
    float* sc  = sm + OFF_SC;   // [BQ][SQ] score rows
    float* ktT = sm + OFF_KT;   // K tile transposed [64][132]
    float* vt  = sm + OFF_KT;   // V tile [128][64] (union, phase-separated)
    float* qsT = sm + OFF_QS;   // Q tile transposed [64][36]
    float* rb  = sm + OFF_RB;   // rel bias dots [BQ][34]

    int b = blockIdx.z, h = blockIdx.y;
    int q0 = blockIdx.x * BQ;
    int t = threadIdx.x;

    const float* qp = g_q + (size_t)((b * NH + h) * SQ) * DH;
    const float* kp = g_k + (size_t)((b * NH + h) * SQ) * DH;
    const float* vp = g_v + (size_t)((b * NH + h) * SQ) * DH;

    // load Q tile transposed
    for (int flat = t; flat < BQ * DH; flat += 256) {
        int d = flat & 63, ql = flat >> 6;
        qsT[d * QS_STRIDE + ql] = qp[(q0 + ql) * DH + d];
    }
    __syncthreads();

    // rb[qi][r] = dot(q_qi, table_r), r in [0,32] (causal => only these used)
    for (int idx = t; idx < BQ * 33; idx += 256) {
        int qi = idx / 33, r = idx - qi * 33;
        float s = 0.f;
        const float* tr = g_table + r * DH;
#pragma unroll 16
        for (int d = 0; d < DH; d++) s += qsT[d * QS_STRIDE + qi] * tr[d];
        rb[qi * RB_STRIDE + r] = s;
    }

    int nk = q0 + BQ;
    int ntiles = (nk + KT - 1) / KT;
    int ty = t >> 5, tx = t & 31;

    // ---- scores: sc[qi][k] = (q.k + relbias) / 8 ----
    for (int tile = 0; tile < ntiles; tile++) {
        int kb = tile * KT;
        __syncthreads();
        for (int flat = t; flat < KT * DH; flat += 256) {
            int d = flat & 63, kl = flat >> 6;
            ktT[d * KT_STRIDE + kl] = kp[(kb + kl) * DH + d];
        }
        __syncthreads();

        float acc[4][4];
#pragma unroll
        for (int i = 0; i < 4; i++)
#pragma unroll
            for (int j = 0; j < 4; j++) acc[i][j] = 0.f;

#pragma unroll 8
        for (int d = 0; d < DH; d++) {
            float4 kv = *(const float4*)&ktT[d * KT_STRIDE + tx * 4];
            float4 qv = *(const float4*)&qsT[d * QS_STRIDE + ty * 4];
            float kr[4] = {kv.x, kv.y, kv.z, kv.w};
            float qr[4] = {qv.x, qv.y, qv.z, qv.w};
#pragma unroll
            for (int i = 0; i < 4; i++)
#pragma unroll
                for (int j = 0; j < 4; j++) acc[i][j] += qr[i] * kr[j];
        }

#pragma unroll
        for (int i = 0; i < 4; i++) {
            int qi = ty * 4 + i;
            int q = q0 + qi;
            float4 o;
            float* op = &o.x;
#pragma unroll
            for (int j = 0; j < 4; j++) {
                int k = kb + tx * 4 + j;
                int ridx = k - q + PCLIP;
                ridx = ridx < 0 ? 0 : (ridx > 32 ? 32 : ridx);
                op[j] = (acc[i][j] + rb[qi * RB_STRIDE + ridx]) * 0.125f;
            }
            *(float4*)&sc[qi * SQ + kb + tx * 4] = o;
        }
    }
    __syncthreads();

    // ---- softmax: 8 lanes per row ----
    {
        int qi8 = t >> 3, ln = t & 7;
        int q = q0 + qi8;
        float* row = sc + qi8 * SQ;
        float mx = -1e30f;
        for (int k = ln; k <= q; k += 8) mx = fmaxf(mx, row[k]);
#pragma unroll
        for (int o = 4; o; o >>= 1) mx = fmaxf(mx, __shfl_xor_sync(0xffffffffu, mx, o));
        float sum = 0.f;
        for (int k = ln; k <= q; k += 8) { float e = expf(row[k] - mx); row[k] = e; sum += e; }
#pragma unroll
        for (int o = 4; o; o >>= 1) sum += __shfl_xor_sync(0xffffffffu, sum, o);
        float inv = 1.0f / sum;
        for (int k = ln; k <= q; k += 8) row[k] *= inv;
        int kend = ntiles * KT;
        for (int k = q + 1 + ln; k < kend; k += 8) row[k] = 0.f;
    }
    __syncthreads();

    // ---- P.V + collapsed rel-pos value term ----
    int qi = t >> 3;
    int dbase = (t & 7) * 8;
    int q = q0 + qi;
    float o[8];
#pragma unroll
    for (int dd = 0; dd < 8; dd++) o[dd] = 0.f;

    for (int tile = 0; tile < ntiles; tile++) {
        int kb = tile * KT;
        {
            const float4* src = (const float4*)(vp + (size_t)kb * DH);
            float4* dstv = (float4*)vt;
            for (int i = t; i < KT * DH / 4; i += 256) dstv[i] = src[i];
        }
        __syncthreads();
        if (q >= kb) {
            int klim = q - kb + 1;
            if (klim > KT) klim = KT;
            klim = (klim + 3) & ~3;                  // p is zero past q
            const float* pr = sc + qi * SQ + kb;
            for (int k = 0; k < klim; k += 4) {
                float4 p4 = *(const float4*)&pr[k];
                float pv[4] = {p4.x, p4.y, p4.z, p4.w};
#pragma unroll
                for (int u = 0; u < 4; u++) {
                    float p = pv[u];
                    const float* vrow = vt + (k + u) * DH + dbase;
                    float4 v0 = *(const float4*)vrow;
                    float4 v1 = *(const float4*)(vrow + 4);
                    o[0] += p * v0.x; o[1] += p * v0.y;
                    o[2] += p * v0.z; o[3] += p * v0.w;
                    o[4] += p * v1.x; o[5] += p * v1.y;
                    o[6] += p * v1.z; o[7] += p * v1.w;
                }
            }
        }
        __syncthreads();
    }

    // rel-value: buckets 1..32 are single probs at k=q-32+r; bucket 0 = 1 - tail
    {
        int qlo = q - 31; if (qlo < 0) qlo = 0;
        const float* row = sc + qi * SQ;
        float tail = 0.f;
        for (int k = qlo; k <= q; k++) tail += row[k];
        float b0 = 1.0f - tail;                      // ~0 when q < 32
        const float* t0 = g_table + dbase;
#pragma unroll
        for (int dd = 0; dd < 8; dd++) o[dd] += b0 * t0[dd];
        for (int k = qlo; k <= q; k++) {
            float p = row[k];
            const float* tr = g_table + (k - q + PCLIP) * DH + dbase;
#pragma unroll
            for (int dd = 0; dd < 8; dd++) o[dd] += p * tr[dd];
        }
        float* op = g_att + (size_t)(b * SQ + q) * DM + h * DH + dbase;
        *(float4*)op       = make_float4(o[0], o[1], o[2], o[3]);
        *(float4*)(op + 4) = make_float4(o[4], o[5], o[6], o[7]);
    }
}

// ---------------- layernorm (unbiased std, /(std+eps)) -------------------
__global__ void ln_kernel(const float* __restrict__ w, const float* __restrict__ bvec,
                          float* __restrict__ out) {
    int m = blockIdx.x;
    int t = threadIdx.x;
    const float4* x4 = (const float4*)(g_x + (size_t)m * DM);
    float4 v = x4[t];
    float s = v.x + v.y + v.z + v.w;
#pragma unroll
    for (int o = 16; o; o >>= 1) s += __shfl_xor_sync(0xffffffffu, s, o);
    __shared__ float sh[4];
    if ((t & 31) == 0) sh[t >> 5] = s;
    __syncthreads();
    float mean = (sh[0] + sh[1] + sh[2] + sh[3]) * (1.0f / (float)DM);

    float dx = v.x - mean, dy = v.y - mean, dz = v.z - mean, dw = v.w - mean;
    float s2 = dx * dx + dy * dy + dz * dz + dw * dw;
#pragma unroll
    for (int o = 16; o; o >>= 1) s2 += __shfl_xor_sync(0xffffffffu, s2, o);
    __syncthreads();
    if ((t & 31) == 0) sh[t >> 5] = s2;
    __syncthreads();
    float var = (sh[0] + sh[1] + sh[2] + sh[3]) * (1.0f / (float)(DM - 1));
    float inv = 1.0f / (sqrtf(var) + 1e-6f);

    float4 wv = ((const float4*)w)[t];
    float4 bb = ((const float4*)bvec)[t];
    float4 r;
    r.x = wv.x * dx * inv + bb.x;
    r.y = wv.y * dy * inv + bb.y;
    r.z = wv.z * dz * inv + bb.z;
    r.w = wv.w * dw * inv + bb.w;
    ((float4*)out)[(size_t)m * (DM / 4) + t] = r;
}

// ---------------- launch --------------------------------------------------
extern "C" void kernel_launch(void* const* d_in, const int* in_sizes, int n_in,
                              void* d_out, int out_size) {
    const float* query = (const float*)d_in[0];
    const float* key   = (const float*)d_in[1];
    const float* value = (const float*)d_in[2];
    const float* Wq = (const float*)d_in[3];
    const float* bq = (const float*)d_in[4];
    const float* Wk = (const float*)d_in[5];
    const float* bk = (const float*)d_in[6];
    const float* Wv = (const float*)d_in[7];
    const float* bv = (const float*)d_in[8];
    const float* Wo = (const float*)d_in[9];
    const float* bo = (const float*)d_in[10];
    const float* lnw = (const float*)d_in[11];
    const float* lnb = (const float*)d_in[12];
    float* out = (float*)d_out;

    table_kernel<<<(NREL * DH + 255) / 256, 256>>>();

    dim3 gg(DM / 64, (NB * SQ) / 64);
    gemm64<0><<<gg, 256>>>(query, Wq, bq, nullptr, 0, NB * SQ, DM, DM);
    gemm64<0><<<gg, 256>>>(key,   Wk, bk, nullptr, 1, NB * SQ, DM, DM);
    gemm64<0><<<gg, 256>>>(value, Wv, bv, nullptr, 2, NB * SQ, DM, DM);

    cudaFuncSetAttribute(attn_kernel, cudaFuncAttributeMaxDynamicSharedMemorySize,
                         ATTN_SMEM_BYTES);
    attn_kernel<<<dim3(SQ / BQ, NH, NB), 256, ATTN_SMEM_BYTES>>>();

    gemm64<1><<<gg, 256>>>(nullptr, Wo, bo, query, 0, NB * SQ, DM, DM);

    ln_kernel<<<NB * SQ, 128>>>(lnw, lnb, out);
}

// round 2
// speedup vs baseline: 1.4160x; 1.4160x over previous
#include <cuda_runtime.h>
#include <math.h>

#define NB 2
#define NH 8
#define BH (NB*NH)
#define SQ 1024
#define DH 64
#define DM 512
#define NREL 65

// ---------------- scratch (device globals: no allocation allowed) ----------
__device__ float g_table[NREL * DH];              // sin-cos rel-pos table
__device__ float g_q[BH * SQ * DH];               // [B,H,S,DH]
__device__ float g_k[BH * SQ * DH];
__device__ float g_v[BH * SQ * DH];
__device__ float g_rb[BH * SQ * 33];              // rel bias dots
__device__ float g_p[(size_t)BH * SQ * SQ];       // scores -> probs (67MB)
__device__ float g_att[NB * SQ * DM];             // attention out [B,S,DM]
__device__ float g_x[NB * SQ * DM];               // pre-LN activations

// ---------------- sincos table -------------------------------------------
__global__ void table_kernel() {
    int i = blockIdx.x * blockDim.x + threadIdx.x;
    if (i >= NREL * DH) return;
    int pos = i / DH, d = i % DH;
    float freq = expf((float)(d & ~1) * (-logf(10000.0f) / (float)DH));
    float a = (float)pos * freq;
    g_table[i] = (d & 1) ? cosf(a) : sinf(a);
}

// ---------------- GEMM: C = A[M,K] @ W[N,K]^T + bias ----------------------
// 128x64 tile, 256 threads, 8x4 micro-tile.
// MODE 0: z in {0,1,2} selects (A,W,bias) and scatters into q/k/v [B,H,S,DH]
// MODE 1: A = g_att, dst = g_x, adds residual
template <int MODE>
__global__ __launch_bounds__(256) void gemm128(
    const float* __restrict__ A0, const float* __restrict__ A1,
    const float* __restrict__ A2,
    const float* __restrict__ W0, const float* __restrict__ W1,
    const float* __restrict__ W2,
    const float* __restrict__ bb0, const float* __restrict__ bb1,
    const float* __restrict__ bb2,
    const float* __restrict__ resid)
{
    __shared__ __align__(16) float As[16][132];   // [k][m] transposed
    __shared__ __align__(16) float Bs[16][68];    // [k][n] transposed

    const float* A; const float* W; const float* bias; float* dst;
    if (MODE == 0) {
        int z = blockIdx.z;
        A    = (z == 0) ? A0  : (z == 1) ? A1  : A2;
        W    = (z == 0) ? W0  : (z == 1) ? W1  : W2;
        bias = (z == 0) ? bb0 : (z == 1) ? bb1 : bb2;
        dst  = (z == 0) ? g_q : (z == 1) ? g_k : g_v;
    } else {
        A = g_att; W = W0; bias = bb0; dst = g_x;
    }

    int m0 = blockIdx.y * 128;
    int n0 = blockIdx.x * 64;
    int t  = threadIdx.x;
    int ty = t >> 4, tx = t & 15;

    float acc[8][4];
#pragma unroll
    for (int i = 0; i < 8; i++)
#pragma unroll
        for (int j = 0; j < 4; j++) acc[i][j] = 0.f;

    for (int k0 = 0; k0 < DM; k0 += 16) {
#pragma unroll
        for (int p = 0; p < 8; p++) {
            int f = t + p * 256;
            int kk = f & 15, mm = f >> 4;
            As[kk][mm] = A[(m0 + mm) * DM + k0 + kk];
        }
#pragma unroll
        for (int p = 0; p < 4; p++) {
            int f = t + p * 256;
            int kk = f & 15, nn = f >> 4;
            Bs[kk][nn] = W[(n0 + nn) * DM + k0 + kk];
        }
        __syncthreads();
#pragma unroll
        for (int kk = 0; kk < 16; kk++) {
            float4 a0 = *(const float4*)&As[kk][ty * 8];
            float4 a1 = *(const float4*)&As[kk][ty * 8 + 4];
            float4 b4 = *(const float4*)&Bs[kk][tx * 4];
            float av[8] = {a0.x, a0.y, a0.z, a0.w, a1.x, a1.y, a1.z, a1.w};
            float bv[4] = {b4.x, b4.y, b4.z, b4.w};
#pragma unroll
            for (int i = 0; i < 8; i++)
#pragma unroll
                for (int j = 0; j < 4; j++) acc[i][j] += av[i] * bv[j];
        }
        __syncthreads();
    }

    float4 b4 = *(const float4*)&bias[n0 + tx * 4];
    float bv[4] = {b4.x, b4.y, b4.z, b4.w};

#pragma unroll
    for (int i = 0; i < 8; i++) {
        int m = m0 + ty * 8 + i;
        if (MODE == 0) {
            int b = m >> 10, s = m & (SQ - 1);
            int h = n0 >> 6;                       // n0 multiple of 64, DH=64
            float4 o = make_float4(acc[i][0] + bv[0], acc[i][1] + bv[1],
                                   acc[i][2] + bv[2], acc[i][3] + bv[3]);
            *(float4*)&dst[(((size_t)(b * NH + h) * SQ) + s) * DH + tx * 4] = o;
        } else {
            float4 r = *(const float4*)&resid[(size_t)m * DM + n0 + tx * 4];
            float4 o = make_float4(acc[i][0] + bv[0] + r.x, acc[i][1] + bv[1] + r.y,
                                   acc[i][2] + bv[2] + r.z, acc[i][3] + bv[3] + r.w);
            *(float4*)&dst[(size_t)m * DM + n0 + tx * 4] = o;
        }
    }
}

// ---------------- rel bias: rb[bh][q][r] = dot(q_vec, table_r), r<33 -------
__global__ void rb_kernel() {
    int idx = blockIdx.x * blockDim.x + threadIdx.x;
    if (idx >= BH * SQ * 33) return;
    int r = idx % 33;
    int rem = idx / 33;
    int q = rem & (SQ - 1);
    int bh = rem >> 10;
    const float* qv = g_q + ((size_t)bh * SQ + q) * DH;
    const float* tr = g_table + r * DH;
    float s = 0.f;
#pragma unroll 16
    for (int d = 0; d < DH; d++) s += qv[d] * tr[d];
    g_rb[idx] = s;
}

// ---------------- scores: 64x64 triangular tiles --------------------------
__global__ __launch_bounds__(128) void scores_kernel() {
    __shared__ __align__(16) float qT[64][68];
    __shared__ __align__(16) float kT[64][68];
    __shared__ float rbs[64][34];

    int id = blockIdx.x;
    int qt = (int)((sqrtf(8.f * (float)id + 1.f) - 1.f) * 0.5f);
    while ((qt + 1) * (qt + 2) / 2 <= id) qt++;
    while (qt * (qt + 1) / 2 > id) qt--;
    int kt = id - qt * (qt + 1) / 2;

    int bh = blockIdx.z;
    int q0 = qt * 64, kb = kt * 64;
    int t = threadIdx.x;

    const float* qp = g_q + (size_t)bh * SQ * DH;
    const float* kp = g_k + (size_t)bh * SQ * DH;

    for (int f = t; f < 64 * 64; f += 128) {
        int d = f & 63, r = f >> 6;
        qT[d][r] = qp[(q0 + r) * DH + d];
    }
    for (int f = t; f < 64 * 64; f += 128) {
        int d = f & 63, r = f >> 6;
        kT[d][r] = kp[(kb + r) * DH + d];
    }
    for (int f = t; f < 64 * 33; f += 128) {
        int r = f / 33, c = f - r * 33;
        rbs[r][c] = g_rb[((size_t)bh * SQ + q0 + r) * 33 + c];
    }
    __syncthreads();

    int ty = t >> 4, tx = t & 15;
    float acc[8][4];
#pragma unroll
    for (int i = 0; i < 8; i++)
#pragma unroll
        for (int j = 0; j < 4; j++) acc[i][j] = 0.f;

#pragma unroll 16
    for (int d = 0; d < 64; d++) {
        float4 a0 = *(const float4*)&qT[d][ty * 8];
        float4 a1 = *(const float4*)&qT[d][ty * 8 + 4];
        float4 b4 = *(const float4*)&kT[d][tx * 4];
        float av[8] = {a0.x, a0.y, a0.z, a0.w, a1.x, a1.y, a1.z, a1.w};
        float bv[4] = {b4.x, b4.y, b4.z, b4.w};
#pragma unroll
        for (int i = 0; i < 8; i++)
#pragma unroll
            for (int j = 0; j < 4; j++) acc[i][j] += av[i] * bv[j];
    }

#pragma unroll
    for (int i = 0; i < 8; i++) {
        int qi = ty * 8 + i;
        int q = q0 + qi;
        float o[4];
#pragma unroll
        for (int j = 0; j < 4; j++) {
            int k = kb + tx * 4 + j;
            int ridx = k - q + 32;
            ridx = ridx < 0 ? 0 : (ridx > 32 ? 32 : ridx);
            o[j] = (acc[i][j] + rbs[qi][ridx]) * 0.125f;
        }
        *(float4*)&g_p[((size_t)bh * SQ + q) * SQ + kb + tx * 4] =
            make_float4(o[0], o[1], o[2], o[3]);
    }
}

// ---------------- softmax: one warp per row, register-resident ------------
__global__ __launch_bounds__(256) void softmax_kernel() {
    int wid = threadIdx.x >> 5, lane = threadIdx.x & 31;
    int row = blockIdx.x * 8 + wid;
    int q = row & (SQ - 1);
    float* p = g_p + (size_t)row * SQ;
    int len = q + 1;

    float ev[32];
    float mx = -3.0e38f;
#pragma unroll
    for (int i = 0; i < 32; i++) {
        int k = lane + i * 32;
        float v = (k < len) ? p[k] : -3.0e38f;
        ev[i] = v;
        mx = fmaxf(mx, v);
    }
#pragma unroll
    for (int o = 16; o; o >>= 1) mx = fmaxf(mx, __shfl_xor_sync(0xffffffffu, mx, o));
    float sum = 0.f;
#pragma unroll
    for (int i = 0; i < 32; i++) {
        float e = __expf(ev[i] - mx);
        ev[i] = e;
        sum += e;
    }
#pragma unroll
    for (int o = 16; o; o >>= 1) sum += __shfl_xor_sync(0xffffffffu, sum, o);
    float inv = 1.0f / sum;
    int fe = ((q >> 6) + 1) << 6;   // zero-fill to 64-boundary for PV tiles
#pragma unroll
    for (int i = 0; i < 32; i++) {
        int k = lane + i * 32;
        if (k < fe) p[k] = (k < len) ? ev[i] * inv : 0.f;
    }
}

// ---------------- P.V + collapsed rel-value tail --------------------------
__global__ __launch_bounds__(128) void pv_kernel() {
    __shared__ __align__(16) float pT[64][68];
    __shared__ __align__(16) float vt[64][68];

    int qt = 15 - (int)blockIdx.y;       // heavy CTAs launch first
    int bh = blockIdx.x;
    int q0 = qt * 64;
    int t = threadIdx.x, ty = t >> 4, tx = t & 15;

    const float* vp = g_v + (size_t)bh * SQ * DH;

    float acc[8][4];
#pragma unroll
    for (int i = 0; i < 8; i++)
#pragma unroll
        for (int j = 0; j < 4; j++) acc[i][j] = 0.f;

    for (int kt = 0; kt <= qt; kt++) {
        int kb = kt * 64;
        __syncthreads();
        for (int f = t; f < 64 * 64; f += 128) {
            int k = f & 63, r = f >> 6;
            pT[k][r] = g_p[((size_t)bh * SQ + q0 + r) * SQ + kb + k];
        }
        for (int f = t; f < 64 * 64; f += 128) {
            int d = f & 63, r = f >> 6;
            vt[r][d] = vp[(kb + r) * DH + d];
        }
        __syncthreads();
#pragma unroll 16
        for (int k = 0; k < 64; k++) {
            float4 a0 = *(const float4*)&pT[k][ty * 8];
            float4 a1 = *(const float4*)&pT[k][ty * 8 + 4];
            float4 b4 = *(const float4*)&vt[k][tx * 4];
            float av[8] = {a0.x, a0.y, a0.z, a0.w, a1.x, a1.y, a1.z, a1.w};
            float bv[4] = {b4.x, b4.y, b4.z, b4.w};
#pragma unroll
            for (int i = 0; i < 8; i++)
#pragma unroll
                for (int j = 0; j < 4; j++) acc[i][j] += av[i] * bv[j];
        }
    }

    int b = bh >> 3, h = bh & 7;
#pragma unroll
    for (int i = 0; i < 8; i++) {
        int q = q0 + ty * 8 + i;
        const float* prow = g_p + ((size_t)bh * SQ + q) * SQ;
        float psum = 0.f;
        float r0 = 0.f, r1 = 0.f, r2 = 0.f, r3 = 0.f;
        for (int ko = 0; ko < 32; ko++) {
            int k = q - 31 + ko;
            if (k >= 0) {
                float pv = __ldg(prow + k);
                psum += pv;
                float4 tv = *(const float4*)&g_table[(ko + 1) * DH + tx * 4];
                r0 += pv * tv.x; r1 += pv * tv.y;
                r2 += pv * tv.z; r3 += pv * tv.w;
            }
        }
        float bmass = 1.0f - psum;                 // bucket-0 probability mass
        float4 t0 = *(const float4*)&g_table[tx * 4];
        float4 o = make_float4(acc[i][0] + r0 + bmass * t0.x,
                               acc[i][1] + r1 + bmass * t0.y,
                               acc[i][2] + r2 + bmass * t0.z,
                               acc[i][3] + r3 + bmass * t0.w);
        *(float4*)&g_att[((size_t)(b * SQ) + q) * DM + h * DH + tx * 4] = o;
    }
}

// ---------------- layernorm (unbiased std, /(std+eps)) -------------------
__global__ void ln_kernel(const float* __restrict__ w, const float* __restrict__ bvec,
                          float* __restrict__ out) {
    int m = blockIdx.x;
    int t = threadIdx.x;
    const float4* x4 = (const float4*)(g_x + (size_t)m * DM);
    float4 v = x4[t];
    float s = v.x + v.y + v.z + v.w;
#pragma unroll
    for (int o = 16; o; o >>= 1) s += __shfl_xor_sync(0xffffffffu, s, o);
    __shared__ float sh[4];
    if ((t & 31) == 0) sh[t >> 5] = s;
    __syncthreads();
    float mean = (sh[0] + sh[1] + sh[2] + sh[3]) * (1.0f / (float)DM);

    float dx = v.x - mean, dy = v.y - mean, dz = v.z - mean, dw = v.w - mean;
    float s2 = dx * dx + dy * dy + dz * dz + dw * dw;
#pragma unroll
    for (int o = 16; o; o >>= 1) s2 += __shfl_xor_sync(0xffffffffu, s2, o);
    __syncthreads();
    if ((t & 31) == 0) sh[t >> 5] = s2;
    __syncthreads();
    float var = (sh[0] + sh[1] + sh[2] + sh[3]) * (1.0f / (float)(DM - 1));
    float inv = 1.0f / (sqrtf(var) + 1e-6f);

    float4 wv = ((const float4*)w)[t];
    float4 bb = ((const float4*)bvec)[t];
    float4 r;
    r.x = wv.x * dx * inv + bb.x;
    r.y = wv.y * dy * inv + bb.y;
    r.z = wv.z * dz * inv + bb.z;
    r.w = wv.w * dw * inv + bb.w;
    ((float4*)out)[(size_t)m * (DM / 4) + t] = r;
}

// ---------------- launch --------------------------------------------------
extern "C" void kernel_launch(void* const* d_in, const int* in_sizes, int n_in,
                              void* d_out, int out_size) {
    const float* query = (const float*)d_in[0];
    const float* key   = (const float*)d_in[1];
    const float* value = (const float*)d_in[2];
    const float* Wq = (const float*)d_in[3];
    const float* bq = (const float*)d_in[4];
    const float* Wk = (const float*)d_in[5];
    const float* bk = (const float*)d_in[6];
    const float* Wv = (const float*)d_in[7];
    const float* bv = (const float*)d_in[8];
    const float* Wo = (const float*)d_in[9];
    const float* bo = (const float*)d_in[10];
    const float* lnw = (const float*)d_in[11];
    const float* lnb = (const float*)d_in[12];
    float* out = (float*)d_out;

    table_kernel<<<(NREL * DH + 255) / 256, 256>>>();

    gemm128<0><<<dim3(DM / 64, (NB * SQ) / 128, 3), 256>>>(
        query, key, value, Wq, Wk, Wv, bq, bk, bv, nullptr);

    rb_kernel<<<(BH * SQ * 33 + 255) / 256, 256>>>();

    scores_kernel<<<dim3(136, 1, BH), 128>>>();

    softmax_kernel<<<BH * SQ / 8, 256>>>();

    pv_kernel<<<dim3(BH, 16), 128>>>();

    gemm128<1><<<dim3(DM / 64, (NB * SQ) / 128, 1), 256>>>(
        nullptr, nullptr, nullptr, Wo, nullptr, nullptr, bo, nullptr, nullptr,
        query);

    ln_kernel<<<NB * SQ, 128>>>(lnw, lnb, out);
}

// round 3
// speedup vs baseline: 2.2047x; 1.5569x over previous
#include <cuda_runtime.h>
#include <math.h>

#define NB 2
#define NH 8
#define BH (NB*NH)
#define SQ 1024
#define DH 64
#define DM 512
#define NREL 65
#define FULLMASK 0xffffffffu

// ---------------- scratch (device globals) --------------------------------
__device__ float g_table[NREL * DH];
__device__ float g_q[BH * SQ * DH];
__device__ float g_k[BH * SQ * DH];
__device__ float g_v[BH * SQ * DH];
__device__ float g_rb[BH * SQ * 33];
__device__ float g_p[(size_t)BH * SQ * SQ];
__device__ float g_att[NB * SQ * DM];
__device__ float g_x[NB * SQ * DM];

// ---------------- tf32 mma helpers ----------------------------------------
__device__ __forceinline__ unsigned f2tf(float f) {
    unsigned u;
    asm("cvt.rna.tf32.f32 %0, %1;" : "=r"(u) : "f"(f));
    return u;
}
__device__ __forceinline__ void mma8(float c[4], const unsigned a[4], const unsigned b[2]) {
    asm volatile(
        "mma.sync.aligned.m16n8k8.row.col.f32.tf32.tf32.f32 "
        "{%0,%1,%2,%3}, {%4,%5,%6,%7}, {%8,%9}, {%0,%1,%2,%3};\n"
        : "+f"(c[0]), "+f"(c[1]), "+f"(c[2]), "+f"(c[3])
        : "r"(a[0]), "r"(a[1]), "r"(a[2]), "r"(a[3]), "r"(b[0]), "r"(b[1]));
}
__device__ __forceinline__ uint4 cvt4(float4 v) {
    uint4 u;
    u.x = f2tf(v.x); u.y = f2tf(v.y); u.z = f2tf(v.z); u.w = f2tf(v.w);
    return u;
}

// ---------------- sincos table -------------------------------------------
__global__ void table_kernel() {
    int i = blockIdx.x * blockDim.x + threadIdx.x;
    if (i >= NREL * DH) return;
    int pos = i / DH, d = i % DH;
    float freq = expf((float)(d & ~1) * (-logf(10000.0f) / (float)DH));
    float a = (float)pos * freq;
    g_table[i] = (d & 1) ? cosf(a) : sinf(a);
}

// ---------------- tensor-core GEMM: C = A[M,K] @ W[N,K]^T + bias ----------
// 128x64 CTA tile, 256 thr = 8 warps (4m x 2n), warp tile 32x32, BK=32.
// MODE 0: z selects (A,W,bias), scatter to q/k/v [B,H,S,DH]
// MODE 1: A = g_att, dst = g_x, adds residual
template <int MODE>
__global__ __launch_bounds__(256) void gemm_tc(
    const float* __restrict__ A0, const float* __restrict__ A1,
    const float* __restrict__ A2,
    const float* __restrict__ W0, const float* __restrict__ W1,
    const float* __restrict__ W2,
    const float* __restrict__ bb0, const float* __restrict__ bb1,
    const float* __restrict__ bb2,
    const float* __restrict__ resid)
{
    __shared__ __align__(16) unsigned As[128 * 36];
    __shared__ __align__(16) unsigned Bs[64 * 36];

    const float *A, *W, *bias; float* dst;
    if (MODE == 0) {
        int z = blockIdx.z;
        A    = (z == 0) ? A0  : (z == 1) ? A1  : A2;
        W    = (z == 0) ? W0  : (z == 1) ? W1  : W2;
        bias = (z == 0) ? bb0 : (z == 1) ? bb1 : bb2;
        dst  = (z == 0) ? g_q : (z == 1) ? g_k : g_v;
    } else { A = g_att; W = W0; bias = bb0; dst = g_x; }

    int m0 = blockIdx.y * 128, n0 = blockIdx.x * 64;
    int t = threadIdx.x, warp = t >> 5, lane = t & 31;
    int g = lane >> 2, t4 = lane & 3;
    int wm = (warp >> 1) * 32, wn = (warp & 1) * 32;

    float c[2][4][4];
#pragma unroll
    for (int i = 0; i < 2; i++)
#pragma unroll
        for (int j = 0; j < 4; j++)
#pragma unroll
            for (int e = 0; e < 4; e++) c[i][j][e] = 0.f;

    for (int k0 = 0; k0 < DM; k0 += 32) {
#pragma unroll
        for (int p = 0; p < 4; p++) {
            int gid = t + p * 256, row = gid >> 3, c4 = (gid & 7) * 4;
            float4 v = *(const float4*)&A[(size_t)(m0 + row) * DM + k0 + c4];
            *(uint4*)&As[row * 36 + c4] = cvt4(v);
        }
#pragma unroll
        for (int p = 0; p < 2; p++) {
            int gid = t + p * 256, row = gid >> 3, c4 = (gid & 7) * 4;
            float4 v = *(const float4*)&W[(size_t)(n0 + row) * DM + k0 + c4];
            *(uint4*)&Bs[row * 36 + c4] = cvt4(v);
        }
        __syncthreads();
#pragma unroll
        for (int kk = 0; kk < 32; kk += 8) {
            unsigned a[2][4], b[4][2];
#pragma unroll
            for (int i = 0; i < 2; i++) {
                int r = wm + 16 * i + g;
                a[i][0] = As[r * 36 + kk + t4];
                a[i][1] = As[(r + 8) * 36 + kk + t4];
                a[i][2] = As[r * 36 + kk + t4 + 4];
                a[i][3] = As[(r + 8) * 36 + kk + t4 + 4];
            }
#pragma unroll
            for (int j = 0; j < 4; j++) {
                int r = wn + 8 * j + g;
                b[j][0] = Bs[r * 36 + kk + t4];
                b[j][1] = Bs[r * 36 + kk + t4 + 4];
            }
#pragma unroll
            for (int i = 0; i < 2; i++)
#pragma unroll
                for (int j = 0; j < 4; j++) mma8(c[i][j], a[i], b[j]);
        }
        __syncthreads();
    }

    float2 bv[4];
#pragma unroll
    for (int j = 0; j < 4; j++)
        bv[j] = *(const float2*)&bias[n0 + wn + 8 * j + 2 * t4];

#pragma unroll
    for (int i = 0; i < 2; i++)
#pragma unroll
        for (int h = 0; h < 2; h++) {
            int m = m0 + wm + 16 * i + g + 8 * h;
#pragma unroll
            for (int j = 0; j < 4; j++) {
                float2 o;
                o.x = c[i][j][2 * h]     + bv[j].x;
                o.y = c[i][j][2 * h + 1] + bv[j].y;
                if (MODE == 0) {
                    int b_ = m >> 10, s = m & (SQ - 1);
                    int head = n0 >> 6, d = wn + 8 * j + 2 * t4;
                    *(float2*)&dst[((size_t)(b_ * NH + head) * SQ + s) * DH + d] = o;
                } else {
                    int n = n0 + wn + 8 * j + 2 * t4;
                    float2 r2 = *(const float2*)&resid[(size_t)m * DM + n];
                    o.x += r2.x; o.y += r2.y;
                    *(float2*)&dst[(size_t)m * DM + n] = o;
                }
            }
        }
}

// ---------------- rel bias: rb[bh][q][r] = dot(q_vec, table_r) ------------
__global__ void rb_kernel() {
    int idx = blockIdx.x * blockDim.x + threadIdx.x;
    if (idx >= BH * SQ * 33) return;
    int r = idx % 33;
    int rem = idx / 33;
    int q = rem & (SQ - 1);
    int bh = rem >> 10;
    const float* qv = g_q + ((size_t)bh * SQ + q) * DH;
    const float* tr = g_table + r * DH;
    float s = 0.f;
#pragma unroll 16
    for (int d = 0; d < DH; d++) s += qv[d] * tr[d];
    g_rb[idx] = s;
}

// ---------------- scores (tc): 128q x 64k triangular tiles ----------------
#define SC_SMEM ((128*68 + 64*68 + 128*34) * 4)
__global__ __launch_bounds__(256) void scores_tc() {
    extern __shared__ __align__(16) unsigned smu[];
    unsigned* Qs = smu;                         // [128][68]
    unsigned* Ks = smu + 128 * 68;              // [64][68]
    float* rbs = (float*)(smu + 128 * 68 + 64 * 68);  // [128][34]

    int id = blockIdx.x, bh = blockIdx.z;
    int qt = (int)((sqrtf(4.f * (float)id + 1.f) - 1.f) * 0.5f);
    while ((qt + 1) * (qt + 2) <= id) qt++;
    while (qt * (qt + 1) > id) qt--;
    int kt = id - qt * (qt + 1);
    int q0 = qt * 128, kb = kt * 64;

    int t = threadIdx.x, warp = t >> 5, lane = t & 31;
    int g = lane >> 2, t4 = lane & 3;
    int wm = (warp >> 1) * 32, wn = (warp & 1) * 32;

    const float* qp = g_q + (size_t)bh * SQ * DH;
    const float* kp = g_k + (size_t)bh * SQ * DH;

#pragma unroll
    for (int p = 0; p < 8; p++) {
        int gid = t + p * 256, row = gid >> 4, c4 = (gid & 15) * 4;
        float4 v = *(const float4*)&qp[(q0 + row) * DH + c4];
        *(uint4*)&Qs[row * 68 + c4] = cvt4(v);
    }
#pragma unroll
    for (int p = 0; p < 4; p++) {
        int gid = t + p * 256, row = gid >> 4, c4 = (gid & 15) * 4;
        float4 v = *(const float4*)&kp[(kb + row) * DH + c4];
        *(uint4*)&Ks[row * 68 + c4] = cvt4(v);
    }
    for (int f = t; f < 128 * 33; f += 256) {
        int r = f / 33, cc = f - r * 33;
        rbs[r * 34 + cc] = g_rb[((size_t)bh * SQ + q0 + r) * 33 + cc];
    }
    __syncthreads();

    float c[2][4][4];
#pragma unroll
    for (int i = 0; i < 2; i++)
#pragma unroll
        for (int j = 0; j < 4; j++)
#pragma unroll
            for (int e = 0; e < 4; e++) c[i][j][e] = 0.f;

#pragma unroll
    for (int kk = 0; kk < 64; kk += 8) {
        unsigned a[2][4], b[4][2];
#pragma unroll
        for (int i = 0; i < 2; i++) {
            int r = wm + 16 * i + g;
            a[i][0] = Qs[r * 68 + kk + t4];
            a[i][1] = Qs[(r + 8) * 68 + kk + t4];
            a[i][2] = Qs[r * 68 + kk + t4 + 4];
            a[i][3] = Qs[(r + 8) * 68 + kk + t4 + 4];
        }
#pragma unroll
        for (int j = 0; j < 4; j++) {
            int r = wn + 8 * j + g;
            b[j][0] = Ks[r * 68 + kk + t4];
            b[j][1] = Ks[r * 68 + kk + t4 + 4];
        }
#pragma unroll
        for (int i = 0; i < 2; i++)
#pragma unroll
            for (int j = 0; j < 4; j++) mma8(c[i][j], a[i], b[j]);
    }

#pragma unroll
    for (int i = 0; i < 2; i++)
#pragma unroll
        for (int h = 0; h < 2; h++) {
            int qi = wm + 16 * i + g + 8 * h;
            int q = q0 + qi;
#pragma unroll
            for (int j = 0; j < 4; j++) {
                int k = kb + wn + 8 * j + 2 * t4;
                float2 o;
#pragma unroll
                for (int e = 0; e < 2; e++) {
                    int ridx = k + e - q + 32;
                    ridx = ridx < 0 ? 0 : (ridx > 32 ? 32 : ridx);
                    float v = (c[i][j][2 * h + e] + rbs[qi * 34 + ridx]) * 0.125f;
                    if (e == 0) o.x = v; else o.y = v;
                }
                *(float2*)&g_p[((size_t)bh * SQ + q) * SQ + k] = o;
            }
        }
}

// ---------------- softmax: one warp per row, register-resident ------------
__global__ __launch_bounds__(256) void softmax_kernel() {
    int wid = threadIdx.x >> 5, lane = threadIdx.x & 31;
    int row = blockIdx.x * 8 + wid;
    int q = row & (SQ - 1);
    float* p = g_p + (size_t)row * SQ;
    int len = q + 1;

    float ev[32];
    float mx = -3.0e38f;
#pragma unroll
    for (int i = 0; i < 32; i++) {
        int k = lane + i * 32;
        float v = (k < len) ? p[k] : -3.0e38f;
        ev[i] = v;
        mx = fmaxf(mx, v);
    }
#pragma unroll
    for (int o = 16; o; o >>= 1) mx = fmaxf(mx, __shfl_xor_sync(FULLMASK, mx, o));
    float sum = 0.f;
#pragma unroll
    for (int i = 0; i < 32; i++) {
        float e = __expf(ev[i] - mx);
        ev[i] = e;
        sum += e;
    }
#pragma unroll
    for (int o = 16; o; o >>= 1) sum += __shfl_xor_sync(FULLMASK, sum, o);
    float inv = 1.0f / sum;
    int fe = ((q >> 7) + 1) << 7;   // zero-fill to 128-boundary for tc PV tiles
#pragma unroll
    for (int i = 0; i < 32; i++) {
        int k = lane + i * 32;
        if (k < fe) p[k] = (k < len) ? ev[i] * inv : 0.f;
    }
}

// ---------------- PV (tc): 128q x 64d, loop 64-wide k tiles ---------------
#define PV_SMEM ((128*68 + 64*72) * 4)
__global__ __launch_bounds__(256) void pv_tc() {
    extern __shared__ __align__(16) unsigned smu[];
    unsigned* Ps = smu;              // [128][68]
    unsigned* Vs = smu + 128 * 68;   // [64][72]  (k rows, d cols)

    int bh = blockIdx.x;
    int qt = 7 - (int)blockIdx.y;    // heavy first
    int q0 = qt * 128;

    int t = threadIdx.x, warp = t >> 5, lane = t & 31;
    int g = lane >> 2, t4 = lane & 3;
    int wm = (warp >> 1) * 32, wn = (warp & 1) * 32;

    const float* vp = g_v + (size_t)bh * SQ * DH;
    const float* pp = g_p + (size_t)bh * SQ * SQ;

    float c[2][4][4];
#pragma unroll
    for (int i = 0; i < 2; i++)
#pragma unroll
        for (int j = 0; j < 4; j++)
#pragma unroll
            for (int e = 0; e < 4; e++) c[i][j][e] = 0.f;

    int nkt = 2 * qt + 2;
    for (int kt = 0; kt < nkt; kt++) {
        int kb = kt * 64;
        __syncthreads();
#pragma unroll
        for (int p = 0; p < 8; p++) {
            int gid = t + p * 256, row = gid >> 4, c4 = (gid & 15) * 4;
            float4 v = *(const float4*)&pp[(size_t)(q0 + row) * SQ + kb + c4];
            *(uint4*)&Ps[row * 68 + c4] = cvt4(v);
        }
#pragma unroll
        for (int p = 0; p < 4; p++) {
            int gid = t + p * 256, row = gid >> 4, c4 = (gid & 15) * 4;
            float4 v = *(const float4*)&vp[(kb + row) * DH + c4];
            *(uint4*)&Vs[row * 72 + c4] = cvt4(v);
        }
        __syncthreads();
#pragma unroll
        for (int kk = 0; kk < 64; kk += 8) {
            unsigned a[2][4], b[4][2];
#pragma unroll
            for (int i = 0; i < 2; i++) {
                int r = wm + 16 * i + g;
                a[i][0] = Ps[r * 68 + kk + t4];
                a[i][1] = Ps[(r + 8) * 68 + kk + t4];
                a[i][2] = Ps[r * 68 + kk + t4 + 4];
                a[i][3] = Ps[(r + 8) * 68 + kk + t4 + 4];
            }
#pragma unroll
            for (int j = 0; j < 4; j++) {
                int col = wn + 8 * j + g;
                b[j][0] = Vs[(kk + t4) * 72 + col];
                b[j][1] = Vs[(kk + t4 + 4) * 72 + col];
            }
#pragma unroll
            for (int i = 0; i < 2; i++)
#pragma unroll
                for (int j = 0; j < 4; j++) mma8(c[i][j], a[i], b[j]);
        }
    }

    int b_ = bh >> 3, head = bh & 7;
#pragma unroll
    for (int i = 0; i < 2; i++)
#pragma unroll
        for (int h = 0; h < 2; h++) {
            int q = q0 + wm + 16 * i + g + 8 * h;
#pragma unroll
            for (int j = 0; j < 4; j++) {
                int d = wn + 8 * j + 2 * t4;
                float2 o = make_float2(c[i][j][2 * h], c[i][j][2 * h + 1]);
                *(float2*)&g_att[((size_t)(b_ * SQ) + q) * DM + head * DH + d] = o;
            }
        }
}

// ---------------- rel-value tail: one warp per (bh,q) row ------------------
__global__ __launch_bounds__(256) void tail_kernel() {
    __shared__ float st[33 * 64];
    int t = threadIdx.x;
    for (int f = t; f < 33 * 64; f += 256) st[f] = g_table[f];
    __syncthreads();

    int wid = t >> 5, lane = t & 31;
    int row = blockIdx.x * 8 + wid;
    int bh = row >> 10, q = row & (SQ - 1);

    int k = q - 31 + lane;
    float pv = (k >= 0) ? g_p[((size_t)bh * SQ + q) * SQ + k] : 0.f;
    float psum = pv;
#pragma unroll
    for (int o = 16; o; o >>= 1) psum += __shfl_xor_sync(FULLMASK, psum, o);

    int d0 = lane, d1 = lane + 32;
    float a0 = 0.f, a1 = 0.f;
#pragma unroll
    for (int ko = 0; ko < 32; ko++) {
        float p = __shfl_sync(FULLMASK, pv, ko);
        a0 += p * st[(ko + 1) * 64 + d0];
        a1 += p * st[(ko + 1) * 64 + d1];
    }
    float bmass = 1.0f - psum;
    a0 += bmass * st[d0];
    a1 += bmass * st[d1];

    int b_ = bh >> 3, head = bh & 7;
    float* op = g_att + ((size_t)(b_ * SQ) + q) * DM + head * DH;
    op[d0] += a0;
    op[d1] += a1;
}

// ---------------- layernorm (unbiased std, /(std+eps)) -------------------
__global__ void ln_kernel(const float* __restrict__ w, const float* __restrict__ bvec,
                          float* __restrict__ out) {
    int m = blockIdx.x;
    int t = threadIdx.x;
    const float4* x4 = (const float4*)(g_x + (size_t)m * DM);
    float4 v = x4[t];
    float s = v.x + v.y + v.z + v.w;
#pragma unroll
    for (int o = 16; o; o >>= 1) s += __shfl_xor_sync(FULLMASK, s, o);
    __shared__ float sh[4];
    if ((t & 31) == 0) sh[t >> 5] = s;
    __syncthreads();
    float mean = (sh[0] + sh[1] + sh[2] + sh[3]) * (1.0f / (float)DM);

    float dx = v.x - mean, dy = v.y - mean, dz = v.z - mean, dw = v.w - mean;
    float s2 = dx * dx + dy * dy + dz * dz + dw * dw;
#pragma unroll
    for (int o = 16; o; o >>= 1) s2 += __shfl_xor_sync(FULLMASK, s2, o);
    __syncthreads();
    if ((t & 31) == 0) sh[t >> 5] = s2;
    __syncthreads();
    float var = (sh[0] + sh[1] + sh[2] + sh[3]) * (1.0f / (float)(DM - 1));
    float inv = 1.0f / (sqrtf(var) + 1e-6f);

    float4 wv = ((const float4*)w)[t];
    float4 bb = ((const float4*)bvec)[t];
    float4 r;
    r.x = wv.x * dx * inv + bb.x;
    r.y = wv.y * dy * inv + bb.y;
    r.z = wv.z * dz * inv + bb.z;
    r.w = wv.w * dw * inv + bb.w;
    ((float4*)out)[(size_t)m * (DM / 4) + t] = r;
}

// ---------------- launch --------------------------------------------------
extern "C" void kernel_launch(void* const* d_in, const int* in_sizes, int n_in,
                              void* d_out, int out_size) {
    const float* query = (const float*)d_in[0];
    const float* key   = (const float*)d_in[1];
    const float* value = (const float*)d_in[2];
    const float* Wq = (const float*)d_in[3];
    const float* bq = (const float*)d_in[4];
    const float* Wk = (const float*)d_in[5];
    const float* bk = (const float*)d_in[6];
    const float* Wv = (const float*)d_in[7];
    const float* bv = (const float*)d_in[8];
    const float* Wo = (const float*)d_in[9];
    const float* bo = (const float*)d_in[10];
    const float* lnw = (const float*)d_in[11];
    const float* lnb = (const float*)d_in[12];
    float* out = (float*)d_out;

    table_kernel<<<(NREL * DH + 255) / 256, 256>>>();

    gemm_tc<0><<<dim3(DM / 64, (NB * SQ) / 128, 3), 256>>>(
        query, key, value, Wq, Wk, Wv, bq, bk, bv, nullptr);

    rb_kernel<<<(BH * SQ * 33 + 255) / 256, 256>>>();

    cudaFuncSetAttribute(scores_tc, cudaFuncAttributeMaxDynamicSharedMemorySize,
                         SC_SMEM);
    scores_tc<<<dim3(72, 1, BH), 256, SC_SMEM>>>();

    softmax_kernel<<<BH * SQ / 8, 256>>>();

    cudaFuncSetAttribute(pv_tc, cudaFuncAttributeMaxDynamicSharedMemorySize,
                         PV_SMEM);
    pv_tc<<<dim3(BH, 8), 256, PV_SMEM>>>();

    tail_kernel<<<BH * SQ / 8, 256>>>();

    gemm_tc<1><<<dim3(DM / 64, (NB * SQ) / 128, 1), 256>>>(
        nullptr, nullptr, nullptr, Wo, nullptr, nullptr, bo, nullptr, nullptr,
        query);

    ln_kernel<<<NB * SQ, 128>>>(lnw, lnb, out);
}

// round 4
// speedup vs baseline: 2.2318x; 1.0123x over previous
#include <cuda_runtime.h>
#include <math.h>

#define NB 2
#define NH 8
#define BH (NB*NH)
#define SQ 1024
#define DH 64
#define DM 512
#define NREL 65
#define FULLMASK 0xffffffffu

// ---------------- scratch (device globals) --------------------------------
__device__ float g_table[NREL * DH];
__device__ float g_q[BH * SQ * DH];
__device__ float g_k[BH * SQ * DH];
__device__ float g_vt[BH * DH * SQ];              // V transposed: [bh][d][s]
__device__ float g_rb[BH * SQ * 33];
__device__ float g_p[(size_t)BH * SQ * SQ];
__device__ float g_att[NB * SQ * DM];
__device__ float g_x[NB * SQ * DM];

// ---------------- tf32 mma helpers ----------------------------------------
__device__ __forceinline__ unsigned f2tf(float f) {
    unsigned u;
    asm("cvt.rna.tf32.f32 %0, %1;" : "=r"(u) : "f"(f));
    return u;
}
__device__ __forceinline__ void mma8(float c[4], const unsigned a[4], const unsigned b[2]) {
    asm volatile(
        "mma.sync.aligned.m16n8k8.row.col.f32.tf32.tf32.f32 "
        "{%0,%1,%2,%3}, {%4,%5,%6,%7}, {%8,%9}, {%0,%1,%2,%3};\n"
        : "+f"(c[0]), "+f"(c[1]), "+f"(c[2]), "+f"(c[3])
        : "r"(a[0]), "r"(a[1]), "r"(a[2]), "r"(a[3]), "r"(b[0]), "r"(b[1]));
}

// store one 8-element k-group with pair permutation: slots [k0,k4,k1,k5,k2,k6,k3,k7]
__device__ __forceinline__ void st_group(unsigned* dst, const float* src) {
    float4 lo = *(const float4*)src;
    float4 hi = *(const float4*)(src + 4);
    uint4 u0; u0.x = f2tf(lo.x); u0.y = f2tf(hi.x); u0.z = f2tf(lo.y); u0.w = f2tf(hi.y);
    uint4 u1; u1.x = f2tf(lo.z); u1.y = f2tf(hi.z); u1.z = f2tf(lo.w); u1.w = f2tf(hi.w);
    *(uint4*)dst = u0;
    *(uint4*)(dst + 4) = u1;
}
// a-frag (16x8) from paired layout: off = kk + 2*t4
__device__ __forceinline__ void lda(unsigned a[4], const unsigned* S, int row,
                                    int stride, int off) {
    uint2 p0 = *(const uint2*)(S + row * stride + off);
    uint2 p1 = *(const uint2*)(S + (row + 8) * stride + off);
    a[0] = p0.x; a[1] = p1.x; a[2] = p0.y; a[3] = p1.y;
}
__device__ __forceinline__ void ldb(unsigned b[2], const unsigned* S, int row,
                                    int stride, int off) {
    uint2 q = *(const uint2*)(S + row * stride + off);
    b[0] = q.x; b[1] = q.y;
}

// ---------------- sincos table -------------------------------------------
__global__ void table_kernel() {
    int i = blockIdx.x * blockDim.x + threadIdx.x;
    if (i >= NREL * DH) return;
    int pos = i / DH, d = i % DH;
    float freq = expf((float)(d & ~1) * (-logf(10000.0f) / (float)DH));
    float a = (float)pos * freq;
    g_table[i] = (d & 1) ? cosf(a) : sinf(a);
}

// ---------------- tensor-core GEMM: C = A[M,K] @ W[N,K]^T + bias ----------
// 128x128 CTA tile, 8 warps (4m x 2n), warp tile 32x64, BK=64.
// MODE 0: z selects (A,W,bias); z<2 scatter to q/k [B,H,S,DH]; z==2 -> g_vt
// MODE 1: A = g_att, dst = g_x, adds residual
#define GE_STRIDE 72
#define GE_SMEM (2 * 128 * GE_STRIDE * 4)
template <int MODE>
__global__ __launch_bounds__(256, 2) void gemm_tc(
    const float* __restrict__ A0, const float* __restrict__ A1,
    const float* __restrict__ A2,
    const float* __restrict__ W0, const float* __restrict__ W1,
    const float* __restrict__ W2,
    const float* __restrict__ bb0, const float* __restrict__ bb1,
    const float* __restrict__ bb2,
    const float* __restrict__ resid)
{
    extern __shared__ __align__(16) unsigned sm[];
    unsigned* As = sm;                     // [128][72]
    unsigned* Bs = sm + 128 * GE_STRIDE;   // [128][72]

    const float *A, *W, *bias;
    int z = (MODE == 0) ? blockIdx.z : 0;
    if (MODE == 0) {
        A    = (z == 0) ? A0  : (z == 1) ? A1  : A2;
        W    = (z == 0) ? W0  : (z == 1) ? W1  : W2;
        bias = (z == 0) ? bb0 : (z == 1) ? bb1 : bb2;
    } else { A = g_att; W = W0; bias = bb0; }

    int m0 = blockIdx.y * 128, n0 = blockIdx.x * 128;
    int t = threadIdx.x, warp = t >> 5, lane = t & 31;
    int g = lane >> 2, t4 = lane & 3;
    int wm = (warp >> 1) * 32, wn = (warp & 1) * 64;

    float c[2][8][4];
#pragma unroll
    for (int i = 0; i < 2; i++)
#pragma unroll
        for (int j = 0; j < 8; j++)
#pragma unroll
            for (int e = 0; e < 4; e++) c[i][j][e] = 0.f;

    for (int k0 = 0; k0 < DM; k0 += 64) {
        __syncthreads();
#pragma unroll
        for (int p = 0; p < 4; p++) {
            int f = t + p * 256, row = f >> 3, grp = f & 7;
            st_group(As + row * GE_STRIDE + grp * 8,
                     A + (size_t)(m0 + row) * DM + k0 + grp * 8);
        }
#pragma unroll
        for (int p = 0; p < 4; p++) {
            int f = t + p * 256, row = f >> 3, grp = f & 7;
            st_group(Bs + row * GE_STRIDE + grp * 8,
                     W + (size_t)(n0 + row) * DM + k0 + grp * 8);
        }
        __syncthreads();
#pragma unroll
        for (int kk = 0; kk < 64; kk += 8) {
            int off = kk + 2 * t4;
            unsigned a[2][4], b[8][2];
#pragma unroll
            for (int i = 0; i < 2; i++) lda(a[i], As, wm + 16 * i + g, GE_STRIDE, off);
#pragma unroll
            for (int j = 0; j < 8; j++) ldb(b[j], Bs, wn + 8 * j + g, GE_STRIDE, off);
#pragma unroll
            for (int i = 0; i < 2; i++)
#pragma unroll
                for (int j = 0; j < 8; j++) mma8(c[i][j], a[i], b[j]);
        }
    }

    float2 bv[8];
#pragma unroll
    for (int j = 0; j < 8; j++)
        bv[j] = *(const float2*)&bias[n0 + wn + 8 * j + 2 * t4];

#pragma unroll
    for (int i = 0; i < 2; i++)
#pragma unroll
        for (int h = 0; h < 2; h++) {
            int m = m0 + wm + 16 * i + g + 8 * h;
#pragma unroll
            for (int j = 0; j < 8; j++) {
                int n = n0 + wn + 8 * j + 2 * t4;
                float2 o;
                o.x = c[i][j][2 * h]     + bv[j].x;
                o.y = c[i][j][2 * h + 1] + bv[j].y;
                if (MODE == 0) {
                    int b_ = m >> 10, s = m & (SQ - 1);
                    int head = n >> 6, d = n & 63;
                    if (z == 2) {
                        float* vt = g_vt + ((size_t)(b_ * NH + head) * DH + d) * SQ + s;
                        vt[0] = o.x;
                        vt[SQ] = o.y;
                    } else {
                        float* dst = (z == 0) ? g_q : g_k;
                        *(float2*)&dst[((size_t)(b_ * NH + head) * SQ + s) * DH + d] = o;
                    }
                } else {
                    float2 r2 = *(const float2*)&resid[(size_t)m * DM + n];
                    o.x += r2.x; o.y += r2.y;
                    *(float2*)&g_x[(size_t)m * DM + n] = o;
                }
            }
        }
}

// ---------------- rel bias: rb[bh][q][r] = dot(q_vec, table_r) ------------
__global__ void rb_kernel() {
    int idx = blockIdx.x * blockDim.x + threadIdx.x;
    if (idx >= BH * SQ * 33) return;
    int r = idx % 33;
    int rem = idx / 33;
    int q = rem & (SQ - 1);
    int bh = rem >> 10;
    const float* qv = g_q + ((size_t)bh * SQ + q) * DH;
    const float* tr = g_table + r * DH;
    float s = 0.f;
#pragma unroll 16
    for (int d = 0; d < DH; d++) s += qv[d] * tr[d];
    g_rb[idx] = s;
}

// ---------------- scores (tc): 128q x 128k triangular tiles ---------------
#define SC_STRIDE 72
#define SC_SMEM ((2 * 128 * SC_STRIDE + 128 * 34) * 4)
__global__ __launch_bounds__(256, 2) void scores_tc() {
    extern __shared__ __align__(16) unsigned sm[];
    unsigned* Qs = sm;                        // [128][72]
    unsigned* Ks = sm + 128 * SC_STRIDE;      // [128][72]
    float* rbs = (float*)(sm + 2 * 128 * SC_STRIDE);  // [128][34]

    int id = blockIdx.x, bh = blockIdx.z;
    int qt = (int)((sqrtf(8.f * (float)id + 1.f) - 1.f) * 0.5f);
    while ((qt + 1) * (qt + 2) / 2 <= id) qt++;
    while (qt * (qt + 1) / 2 > id) qt--;
    int kt = id - qt * (qt + 1) / 2;
    int q0 = qt * 128, kb = kt * 128;

    int t = threadIdx.x, warp = t >> 5, lane = t & 31;
    int g = lane >> 2, t4 = lane & 3;
    int wm = (warp >> 1) * 32, wn = (warp & 1) * 64;

    const float* qp = g_q + (size_t)bh * SQ * DH;
    const float* kp = g_k + (size_t)bh * SQ * DH;

#pragma unroll
    for (int p = 0; p < 4; p++) {
        int f = t + p * 256, row = f >> 3, grp = f & 7;
        st_group(Qs + row * SC_STRIDE + grp * 8, qp + (q0 + row) * DH + grp * 8);
    }
#pragma unroll
    for (int p = 0; p < 4; p++) {
        int f = t + p * 256, row = f >> 3, grp = f & 7;
        st_group(Ks + row * SC_STRIDE + grp * 8, kp + (kb + row) * DH + grp * 8);
    }
    for (int f = t; f < 128 * 33; f += 256) {
        int r = f / 33, cc = f - r * 33;
        rbs[r * 34 + cc] = g_rb[((size_t)bh * SQ + q0 + r) * 33 + cc];
    }
    __syncthreads();

    float c[2][8][4];
#pragma unroll
    for (int i = 0; i < 2; i++)
#pragma unroll
        for (int j = 0; j < 8; j++)
#pragma unroll
            for (int e = 0; e < 4; e++) c[i][j][e] = 0.f;

#pragma unroll
    for (int kk = 0; kk < 64; kk += 8) {
        int off = kk + 2 * t4;
        unsigned a[2][4], b[8][2];
#pragma unroll
        for (int i = 0; i < 2; i++) lda(a[i], Qs, wm + 16 * i + g, SC_STRIDE, off);
#pragma unroll
        for (int j = 0; j < 8; j++) ldb(b[j], Ks, wn + 8 * j + g, SC_STRIDE, off);
#pragma unroll
        for (int i = 0; i < 2; i++)
#pragma unroll
            for (int j = 0; j < 8; j++) mma8(c[i][j], a[i], b[j]);
    }

#pragma unroll
    for (int i = 0; i < 2; i++)
#pragma unroll
        for (int h = 0; h < 2; h++) {
            int qi = wm + 16 * i + g + 8 * h;
            int q = q0 + qi;
#pragma unroll
            for (int j = 0; j < 8; j++) {
                int k = kb + wn + 8 * j + 2 * t4;
                float2 o;
#pragma unroll
                for (int e = 0; e < 2; e++) {
                    int ridx = k + e - q + 32;
                    ridx = ridx < 0 ? 0 : (ridx > 32 ? 32 : ridx);
                    float v = (c[i][j][2 * h + e] + rbs[qi * 34 + ridx]) * 0.125f;
                    if (e == 0) o.x = v; else o.y = v;
                }
                *(float2*)&g_p[((size_t)bh * SQ + q) * SQ + k] = o;
            }
        }
}

// ---------------- softmax: one warp per row, register-resident ------------
__global__ __launch_bounds__(256) void softmax_kernel() {
    int wid = threadIdx.x >> 5, lane = threadIdx.x & 31;
    int row = blockIdx.x * 8 + wid;
    int q = row & (SQ - 1);
    float* p = g_p + (size_t)row * SQ;
    int len = q + 1;

    float ev[32];
    float mx = -3.0e38f;
#pragma unroll
    for (int i = 0; i < 32; i++) {
        int k = lane + i * 32;
        float v = (k < len) ? p[k] : -3.0e38f;
        ev[i] = v;
        mx = fmaxf(mx, v);
    }
#pragma unroll
    for (int o = 16; o; o >>= 1) mx = fmaxf(mx, __shfl_xor_sync(FULLMASK, mx, o));
    float sum = 0.f;
#pragma unroll
    for (int i = 0; i < 32; i++) {
        float e = __expf(ev[i] - mx);
        ev[i] = e;
        sum += e;
    }
#pragma unroll
    for (int o = 16; o; o >>= 1) sum += __shfl_xor_sync(FULLMASK, sum, o);
    float inv = 1.0f / sum;
    int fe = ((q >> 7) + 1) << 7;   // zero-fill to 128-boundary for PV tiles
#pragma unroll
    for (int i = 0; i < 32; i++) {
        int k = lane + i * 32;
        if (k < fe) p[k] = (k < len) ? ev[i] * inv : 0.f;
    }
}

// ---------------- PV (tc): 128q x 64d, loop 128-wide k tiles --------------
#define PV_STRIDE 136
#define PV_SMEM ((128 * PV_STRIDE + 64 * PV_STRIDE) * 4)
__global__ __launch_bounds__(256, 2) void pv_tc() {
    extern __shared__ __align__(16) unsigned sm[];
    unsigned* Ps = sm;                        // [128][136]
    unsigned* Vs = sm + 128 * PV_STRIDE;      // [64][136]  (rows = d)

    int bh = blockIdx.x;
    int qt = 7 - (int)blockIdx.y;             // heavy first
    int q0 = qt * 128;

    int t = threadIdx.x, warp = t >> 5, lane = t & 31;
    int g = lane >> 2, t4 = lane & 3;
    int wm = (warp >> 1) * 32, wn = (warp & 1) * 32;

    const float* pp = g_p + (size_t)bh * SQ * SQ;
    const float* vtp = g_vt + (size_t)bh * DH * SQ;

    float c[2][4][4];
#pragma unroll
    for (int i = 0; i < 2; i++)
#pragma unroll
        for (int j = 0; j < 4; j++)
#pragma unroll
            for (int e = 0; e < 4; e++) c[i][j][e] = 0.f;

    for (int kt = 0; kt <= qt; kt++) {
        int kb = kt * 128;
        __syncthreads();
#pragma unroll
        for (int p = 0; p < 8; p++) {
            int f = t + p * 256, row = f >> 4, grp = f & 15;
            st_group(Ps + row * PV_STRIDE + grp * 8,
                     pp + (size_t)(q0 + row) * SQ + kb + grp * 8);
        }
#pragma unroll
        for (int p = 0; p < 4; p++) {
            int f = t + p * 256, row = f >> 4, grp = f & 15;
            st_group(Vs + row * PV_STRIDE + grp * 8,
                     vtp + (size_t)row * SQ + kb + grp * 8);
        }
        __syncthreads();
#pragma unroll
        for (int kk = 0; kk < 128; kk += 8) {
            int off = kk + 2 * t4;
            unsigned a[2][4], b[4][2];
#pragma unroll
            for (int i = 0; i < 2; i++) lda(a[i], Ps, wm + 16 * i + g, PV_STRIDE, off);
#pragma unroll
            for (int j = 0; j < 4; j++) ldb(b[j], Vs, wn + 8 * j + g, PV_STRIDE, off);
#pragma unroll
            for (int i = 0; i < 2; i++)
#pragma unroll
                for (int j = 0; j < 4; j++) mma8(c[i][j], a[i], b[j]);
        }
    }

    int b_ = bh >> 3, head = bh & 7;
#pragma unroll
    for (int i = 0; i < 2; i++)
#pragma unroll
        for (int h = 0; h < 2; h++) {
            int q = q0 + wm + 16 * i + g + 8 * h;
#pragma unroll
            for (int j = 0; j < 4; j++) {
                int d = wn + 8 * j + 2 * t4;
                float2 o = make_float2(c[i][j][2 * h], c[i][j][2 * h + 1]);
                *(float2*)&g_att[((size_t)(b_ * SQ) + q) * DM + head * DH + d] = o;
            }
        }
}

// ---------------- rel-value tail: one warp per (bh,q) row ------------------
__global__ __launch_bounds__(256) void tail_kernel() {
    __shared__ float st[33 * 64];
    int t = threadIdx.x;
    for (int f = t; f < 33 * 64; f += 256) st[f] = g_table[f];
    __syncthreads();

    int wid = t >> 5, lane = t & 31;
    int row = blockIdx.x * 8 + wid;
    int bh = row >> 10, q = row & (SQ - 1);

    int k = q - 31 + lane;
    float pv = (k >= 0) ? g_p[((size_t)bh * SQ + q) * SQ + k] : 0.f;
    float psum = pv;
#pragma unroll
    for (int o = 16; o; o >>= 1) psum += __shfl_xor_sync(FULLMASK, psum, o);

    int d0 = lane, d1 = lane + 32;
    float a0 = 0.f, a1 = 0.f;
#pragma unroll
    for (int ko = 0; ko < 32; ko++) {
        float p = __shfl_sync(FULLMASK, pv, ko);
        a0 += p * st[(ko + 1) * 64 + d0];
        a1 += p * st[(ko + 1) * 64 + d1];
    }
    float bmass = 1.0f - psum;
    a0 += bmass * st[d0];
    a1 += bmass * st[d1];

    int b_ = bh >> 3, head = bh & 7;
    float* op = g_att + ((size_t)(b_ * SQ) + q) * DM + head * DH;
    op[d0] += a0;
    op[d1] += a1;
}

// ---------------- layernorm (unbiased std, /(std+eps)) -------------------
__global__ void ln_kernel(const float* __restrict__ w, const float* __restrict__ bvec,
                          float* __restrict__ out) {
    int m = blockIdx.x;
    int t = threadIdx.x;
    const float4* x4 = (const float4*)(g_x + (size_t)m * DM);
    float4 v = x4[t];
    float s = v.x + v.y + v.z + v.w;
#pragma unroll
    for (int o = 16; o; o >>= 1) s += __shfl_xor_sync(FULLMASK, s, o);
    __shared__ float sh[4];
    if ((t & 31) == 0) sh[t >> 5] = s;
    __syncthreads();
    float mean = (sh[0] + sh[1] + sh[2] + sh[3]) * (1.0f / (float)DM);

    float dx = v.x - mean, dy = v.y - mean, dz = v.z - mean, dw = v.w - mean;
    float s2 = dx * dx + dy * dy + dz * dz + dw * dw;
#pragma unroll
    for (int o = 16; o; o >>= 1) s2 += __shfl_xor_sync(FULLMASK, s2, o);
    __syncthreads();
    if ((t & 31) == 0) sh[t >> 5] = s2;
    __syncthreads();
    float var = (sh[0] + sh[1] + sh[2] + sh[3]) * (1.0f / (float)(DM - 1));
    float inv = 1.0f / (sqrtf(var) + 1e-6f);

    float4 wv = ((const float4*)w)[t];
    float4 bb = ((const float4*)bvec)[t];
    float4 r;
    r.x = wv.x * dx * inv + bb.x;
    r.y = wv.y * dy * inv + bb.y;
    r.z = wv.z * dz * inv + bb.z;
    r.w = wv.w * dw * inv + bb.w;
    ((float4*)out)[(size_t)m * (DM / 4) + t] = r;
}

// ---------------- launch --------------------------------------------------
extern "C" void kernel_launch(void* const* d_in, const int* in_sizes, int n_in,
                              void* d_out, int out_size) {
    const float* query = (const float*)d_in[0];
    const float* key   = (const float*)d_in[1];
    const float* value = (const float*)d_in[2];
    const float* Wq = (const float*)d_in[3];
    const float* bq = (const float*)d_in[4];
    const float* Wk = (const float*)d_in[5];
    const float* bk = (const float*)d_in[6];
    const float* Wv = (const float*)d_in[7];
    const float* bv = (const float*)d_in[8];
    const float* Wo = (const float*)d_in[9];
    const float* bo = (const float*)d_in[10];
    const float* lnw = (const float*)d_in[11];
    const float* lnb = (const float*)d_in[12];
    float* out = (float*)d_out;

    table_kernel<<<(NREL * DH + 255) / 256, 256>>>();

    cudaFuncSetAttribute(gemm_tc<0>, cudaFuncAttributeMaxDynamicSharedMemorySize,
                         GE_SMEM);
    cudaFuncSetAttribute(gemm_tc<1>, cudaFuncAttributeMaxDynamicSharedMemorySize,
                         GE_SMEM);
    gemm_tc<0><<<dim3(DM / 128, (NB * SQ) / 128, 3), 256, GE_SMEM>>>(
        query, key, value, Wq, Wk, Wv, bq, bk, bv, nullptr);

    rb_kernel<<<(BH * SQ * 33 + 255) / 256, 256>>>();

    cudaFuncSetAttribute(scores_tc, cudaFuncAttributeMaxDynamicSharedMemorySize,
                         SC_SMEM);
    scores_tc<<<dim3(36, 1, BH), 256, SC_SMEM>>>();

    softmax_kernel<<<BH * SQ / 8, 256>>>();

    cudaFuncSetAttribute(pv_tc, cudaFuncAttributeMaxDynamicSharedMemorySize,
                         PV_SMEM);
    pv_tc<<<dim3(BH, 8), 256, PV_SMEM>>>();

    tail_kernel<<<BH * SQ / 8, 256>>>();

    gemm_tc<1><<<dim3(DM / 128, (NB * SQ) / 128, 1), 256, GE_SMEM>>>(
        nullptr, nullptr, nullptr, Wo, nullptr, nullptr, bo, nullptr, nullptr,
        query);

    ln_kernel<<<NB * SQ, 128>>>(lnw, lnb, out);
}